// round 3
// baseline (speedup 1.0000x reference)
#include <cuda_runtime.h>

#define NN 100000
#define HH 64
#define EMAX 1600000
#define BN_EPS 1e-5f

// ---- scratch (static device globals; float4-typed for 16B alignment) ----
__device__ float4 g_bufA[NN * HH / 4];
__device__ float4 g_bufB[NN * HH / 4];
__device__ int   g_csr[EMAX];     // src ids grouped by dst
__device__ int   g_cnt[NN];       // in-degree
__device__ int   g_off[NN];       // CSR offsets
__device__ int   g_cur[NN];       // placement cursor
__device__ int   g_is64;
__device__ float g_dinv[NN];
__device__ float g_stats1[128];   // sum[64], sumsq[64]
__device__ float g_stats2[128];

// ---- init: zero counts+stats; block 0 detects int64 vs int32 edge_index ----
__global__ void k_init(const unsigned int* __restrict__ ei) {
    int i = blockIdx.x * 256 + threadIdx.x;
    if (i < NN) g_cnt[i] = 0;
    if (i < 128) { g_stats1[i] = 0.0f; g_stats2[i] = 0.0f; }
    if (blockIdx.x == 0) {
        __shared__ unsigned int s;
        if (threadIdx.x == 0) s = 0u;
        __syncthreads();
        atomicOr(&s, ei[threadIdx.x * 2 + 1]);  // high words if int64
        __syncthreads();
        if (threadIdx.x == 0) g_is64 = (s == 0u) ? 1 : 0;
    }
}

// ---- in-degree of dst ----
__global__ void k_deg(const void* __restrict__ ei, int E) {
    int e = blockIdx.x * 256 + threadIdx.x;
    if (e >= E) return;
    int d = g_is64 ? (int)((const long long*)ei)[E + e] : ((const int*)ei)[E + e];
    atomicAdd(&g_cnt[d], 1);
}

// ---- single-block scan: offsets, cursor copy, dinv ----
__global__ void __launch_bounds__(1024) k_scan() {
    __shared__ int psum[1024];
    const int t = threadIdx.x;
    const int C = (NN + 1023) / 1024;
    int lo = t * C, hi = min(lo + C, NN);
    int s = 0;
    for (int i = lo; i < hi; i++) s += g_cnt[i];
    psum[t] = s;
    __syncthreads();
    for (int off = 1; off < 1024; off <<= 1) {
        int v = (t >= off) ? psum[t - off] : 0;
        __syncthreads();
        psum[t] += v;
        __syncthreads();
    }
    int run = (t == 0) ? 0 : psum[t - 1];
    for (int i = lo; i < hi; i++) {
        int c = g_cnt[i];
        g_off[i] = run;
        g_cur[i] = run;
        g_dinv[i] = rsqrtf((float)c + 1.0f);  // +1 self loop
        run += c;
    }
}

// ---- CSR placement: bucket src by dst ----
__global__ void k_place(const void* __restrict__ ei, int E) {
    int e = blockIdx.x * 256 + threadIdx.x;
    if (e >= E) return;
    int s, d;
    if (g_is64) {
        const long long* p = (const long long*)ei;
        s = (int)p[e]; d = (int)p[E + e];
    } else {
        const int* p = (const int*)ei;
        s = p[e]; d = p[E + e];
    }
    int pos = atomicAdd(&g_cur[d], 1);
    g_csr[pos] = s;
}

// ---- GEMM: out[r] = ((a*X[r]+c) @ W) * rowscale[r] + (bias + c@W)
// a,c derived in-block from BN stats (or identity if stats==null).
template <int NOUT>
__global__ void __launch_bounds__(128) k_gemm(
    const float* __restrict__ X, const float* __restrict__ Wg,
    const float* __restrict__ stats, const float* __restrict__ gamma,
    const float* __restrict__ beta,
    const float* __restrict__ rowscale,
    const float* __restrict__ bias, float* __restrict__ out)
{
    extern __shared__ float sm[];
    float* Xs   = sm;                 // 128 * 65
    float* Ws   = sm + 128 * 65;      // 64 * NOUT (pre-scaled by a[k])
    float* Init = Ws + 64 * NOUT;     // NOUT
    __shared__ float sa[64], sc[64];

    const int t = threadIdx.x;
    const long row0 = (long)blockIdx.x * 128;

    if (t < 64) {
        float a = 1.0f, c = 0.0f;
        if (stats) {
            float mu  = stats[t] * (1.0f / NN);
            float var = stats[64 + t] * (1.0f / NN) - mu * mu;
            a = gamma[t] * rsqrtf(var + BN_EPS);
            c = beta[t] - mu * a;
        }
        sa[t] = a; sc[t] = c;
    }
    __syncthreads();

    #pragma unroll
    for (int i = 0; i < 16; i++) {
        int lin = t + i * 128;
        int r = lin >> 4, q = lin & 15;
        long gr = row0 + r;
        float4 v = (gr < NN) ? reinterpret_cast<const float4*>(X)[gr * 16 + q]
                             : make_float4(0.f, 0.f, 0.f, 0.f);
        float* p = &Xs[r * 65 + q * 4];
        p[0] = v.x; p[1] = v.y; p[2] = v.z; p[3] = v.w;
    }
    #pragma unroll
    for (int i = t; i < 16 * NOUT; i += 128) {
        int k = (i * 4) / NOUT;
        float a = sa[k];
        float4 w = reinterpret_cast<const float4*>(Wg)[i];
        reinterpret_cast<float4*>(Ws)[i] = make_float4(w.x * a, w.y * a, w.z * a, w.w * a);
    }
    if (t < NOUT) {
        float s = bias ? bias[t] : 0.0f;
        #pragma unroll 8
        for (int k = 0; k < 64; k++) s += sc[k] * Wg[k * NOUT + t];
        Init[t] = s;
    }
    __syncthreads();

    unsigned long long acc[NOUT / 2];
    #pragma unroll
    for (int j = 0; j < NOUT / 2; j++) {
        float2 iv = reinterpret_cast<const float2*>(Init)[j];
        asm("mov.b64 %0, {%1, %2};" : "=l"(acc[j]) : "f"(iv.x), "f"(iv.y));
    }
    const float* xr = &Xs[t * 65];
    #pragma unroll 4
    for (int k = 0; k < 64; k++) {
        float xv = xr[k];
        unsigned long long xx;
        asm("mov.b64 %0, {%1, %1};" : "=l"(xx) : "f"(xv));
        const unsigned long long* wr =
            reinterpret_cast<const unsigned long long*>(&Ws[k * NOUT]);
        #pragma unroll
        for (int j = 0; j < NOUT / 2; j++)
            asm("fma.rn.f32x2 %0, %1, %2, %0;" : "+l"(acc[j]) : "l"(xx), "l"(wr[j]));
    }

    long r = row0 + t;
    float rs = 1.0f;
    if (rowscale && r < NN) rs = rowscale[r];

    __syncthreads();
    #pragma unroll
    for (int j = 0; j < NOUT / 2; j++) {
        float lo, hi;
        asm("mov.b64 {%0, %1}, %2;" : "=f"(lo), "=f"(hi) : "l"(acc[j]));
        Xs[t * 65 + 2 * j]     = lo * rs;
        Xs[t * 65 + 2 * j + 1] = hi * rs;
    }
    __syncthreads();
    constexpr int Q = NOUT / 4;
    #pragma unroll
    for (int i = 0; i < Q; i++) {
        int lin = t + i * 128;
        int r2 = lin / Q, q = lin % Q;
        long gr = row0 + r2;
        if (gr < NN) {
            float* p = &Xs[r2 * 65 + q * 4];
            reinterpret_cast<float4*>(out)[gr * Q + q] = make_float4(p[0], p[1], p[2], p[3]);
        }
    }
}

// ---- fused aggregate + epilogue: one warp per node ----
// out[v] = relu(dinv[v] * (hs[v] + sum_{s in CSR[v]} hs[s]) + bias); BN stats.
__global__ void __launch_bounds__(256) k_agg(
    const float2* __restrict__ hs, float2* __restrict__ out,
    const float* __restrict__ bias, float* __restrict__ stats)
{
    const int lane = threadIdx.x & 31;
    const int warp = (blockIdx.x * blockDim.x + threadIdx.x) >> 5;
    const int nwarps = (gridDim.x * blockDim.x) >> 5;
    const float2 b = reinterpret_cast<const float2*>(bias)[lane];
    float2 s1 = make_float2(0.f, 0.f), s2 = make_float2(0.f, 0.f);

    for (int v = warp; v < NN; v += nwarps) {
        const int base = g_off[v];
        const int d = g_cnt[v];
        float2 acc = hs[v * 32 + lane];     // self loop term
        for (int j0 = 0; j0 < d; j0 += 32) {
            int idx = 0;
            if (j0 + lane < d) idx = g_csr[base + j0 + lane];
            const int m = min(32, d - j0);
            int j = 0;
            for (; j + 4 <= m; j += 4) {
                int s0 = __shfl_sync(0xffffffffu, idx, j);
                int sB = __shfl_sync(0xffffffffu, idx, j + 1);
                int sC = __shfl_sync(0xffffffffu, idx, j + 2);
                int sD = __shfl_sync(0xffffffffu, idx, j + 3);
                float2 v0 = hs[s0 * 32 + lane];
                float2 v1 = hs[sB * 32 + lane];
                float2 v2 = hs[sC * 32 + lane];
                float2 v3 = hs[sD * 32 + lane];
                acc.x += (v0.x + v1.x) + (v2.x + v3.x);
                acc.y += (v0.y + v1.y) + (v2.y + v3.y);
            }
            for (; j < m; j++) {
                int s0 = __shfl_sync(0xffffffffu, idx, j);
                float2 v0 = hs[s0 * 32 + lane];
                acc.x += v0.x; acc.y += v0.y;
            }
        }
        const float di = g_dinv[v];
        float2 o;
        o.x = fmaxf(fmaf(di, acc.x, b.x), 0.0f);
        o.y = fmaxf(fmaf(di, acc.y, b.y), 0.0f);
        out[v * 32 + lane] = o;
        s1.x += o.x;       s1.y += o.y;
        s2.x += o.x * o.x; s2.y += o.y * o.y;
    }
    atomicAdd(&stats[2 * lane],      s1.x);
    atomicAdd(&stats[2 * lane + 1],  s1.y);
    atomicAdd(&stats[64 + 2 * lane], s2.x);
    atomicAdd(&stats[65 + 2 * lane], s2.y);
}

extern "C" void kernel_launch(void* const* d_in, const int* in_sizes, int n_in,
                              void* d_out, int out_size)
{
    const float* x      = (const float*)d_in[0];
    const void*  ei     = d_in[1];
    const float* W1     = (const float*)d_in[2];
    const float* b1     = (const float*)d_in[3];
    const float* gamma1 = (const float*)d_in[4];
    const float* beta1  = (const float*)d_in[5];
    const float* W2     = (const float*)d_in[6];
    const float* b2     = (const float*)d_in[7];
    const float* gamma2 = (const float*)d_in[8];
    const float* beta2  = (const float*)d_in[9];
    const float* Wfc    = (const float*)d_in[10];
    const float* bfc    = (const float*)d_in[11];
    float* out = (float*)d_out;

    int E = in_sizes[1] / 2;
    if (E > EMAX) E = EMAX;

    float4 *pA, *pB;
    float *ps1, *ps2, *pdinv;
    cudaGetSymbolAddress((void**)&pA, g_bufA);
    cudaGetSymbolAddress((void**)&pB, g_bufB);
    cudaGetSymbolAddress((void**)&ps1, g_stats1);
    cudaGetSymbolAddress((void**)&ps2, g_stats2);
    cudaGetSymbolAddress((void**)&pdinv, g_dinv);

    const int smem64 = (128 * 65 + 64 * 64 + 64) * (int)sizeof(float);
    const int smem32 = (128 * 65 + 64 * 32 + 32) * (int)sizeof(float);
    cudaFuncSetAttribute(k_gemm<64>, cudaFuncAttributeMaxDynamicSharedMemorySize, smem64);
    cudaFuncSetAttribute(k_gemm<32>, cudaFuncAttributeMaxDynamicSharedMemorySize, smem32);

    const int GB = (NN + 127) / 128;
    const int EB = (E + 255) / 256;

    k_init<<<(NN + 255) / 256, 256>>>((const unsigned int*)ei);
    k_deg<<<EB, 256>>>(ei, E);
    k_scan<<<1, 1024>>>();
    k_place<<<EB, 256>>>(ei, E);

    // layer 1: hs1 = (x@W1)*dinv -> agg+relu+stats -> h1
    k_gemm<64><<<GB, 128, smem64>>>(x, W1, nullptr, nullptr, nullptr,
                                    pdinv, nullptr, (float*)pA);
    k_agg<<<2048, 256>>>((const float2*)pA, (float2*)pB, b1, ps1);

    // layer 2: hs2 = ((a1*h1+c1)@W2)*dinv -> agg+relu+stats -> h2
    k_gemm<64><<<GB, 128, smem64>>>((const float*)pB, W2, ps1, gamma1, beta1,
                                    pdinv, nullptr, (float*)pA);
    k_agg<<<2048, 256>>>((const float2*)pA, (float2*)pB, b2, ps2);

    // final: out = (a2*h2+c2)@Wfc + (bfc + c2@Wfc)
    k_gemm<32><<<GB, 128, smem32>>>((const float*)pB, Wfc, ps2, gamma2, beta2,
                                    nullptr, bfc, out);
}

// round 5
// speedup vs baseline: 1.9174x; 1.9174x over previous
#include <cuda_runtime.h>

#define NN 100000
#define HH 64
#define EMAX 1600000
#define BN_EPS 1e-5f

// ---- scratch (static device globals; float4-typed for 16B alignment) ----
__device__ float4 g_bufA[NN * HH / 4];   // hs1 -> h1
__device__ float4 g_bufB[NN * HH / 4];   // accumulator
__device__ float4 g_bufC[NN * HH / 4];   // hs2 -> h2
__device__ int   g_src[EMAX];
__device__ int   g_dst[EMAX];
__device__ int   g_is64;
__device__ float g_deg[NN];
__device__ float g_dinv[NN];
// stats padded: channel ch lives at [ch*32] -> each on its own 128B line
__device__ float g_stats1[128 * 32];
__device__ float g_stats2[128 * 32];
__device__ float g_bn1[128];             // a[64], c[64]
__device__ float g_bn2[128];

// ---- detect int64 vs int32 edge_index (JAX x64-off demotes to int32) ----
__global__ void k_detect(const unsigned int* __restrict__ ei) {
    __shared__ unsigned int s;
    if (threadIdx.x == 0) s = 0u;
    __syncthreads();
    atomicOr(&s, ei[threadIdx.x * 2 + 1]);   // high words if int64
    __syncthreads();
    if (threadIdx.x == 0) g_is64 = (s == 0u) ? 1 : 0;
}

// ---- convert indices to int32 scratch ----
__global__ void k_cvt(const void* __restrict__ ei, int E) {
    int e = blockIdx.x * 256 + threadIdx.x;
    if (e >= E) return;
    if (g_is64) {
        const long long* p = (const long long*)ei;
        g_src[e] = (int)p[e];
        g_dst[e] = (int)p[e + E];
    } else {
        const int* p = (const int*)ei;
        g_src[e] = p[e];
        g_dst[e] = p[e + E];
    }
}

// ---- zero accumulators / stats / deg ----
__global__ void k_zero() {
    int i = blockIdx.x * 256 + threadIdx.x;
    if (i < NN * HH / 4) g_bufB[i] = make_float4(0.f, 0.f, 0.f, 0.f);
    if (i < NN) g_deg[i] = 0.0f;
    if (i < 128 * 32) { g_stats1[i] = 0.0f; g_stats2[i] = 0.0f; }
}

// ---- degree (in-degree of dst) ----
__global__ void k_deg(int E) {
    int e = blockIdx.x * 256 + threadIdx.x;
    if (e < E) atomicAdd(&g_deg[g_dst[e]], 1.0f);
}

__global__ void k_dinv() {
    int v = blockIdx.x * 256 + threadIdx.x;
    if (v < NN) g_dinv[v] = rsqrtf(g_deg[v] + 1.0f);   // +1 self-loop
}

// ---- GEMM: out[r] = ((a*X[r]+c) @ W) * rowscale[r] + (bias + c@W)
template <int NOUT>
__global__ void __launch_bounds__(128) k_gemm(
    const float* __restrict__ X, const float* __restrict__ Wg,
    const float* __restrict__ bn, const float* __restrict__ rowscale,
    const float* __restrict__ bias, float* __restrict__ out)
{
    extern __shared__ float sm[];
    float* Xs   = sm;                 // 128 * 65 (pad 65 -> conflict-free)
    float* Ws   = sm + 128 * 65;      // 64 * NOUT (pre-scaled by a[k])
    float* Init = Ws + 64 * NOUT;     // NOUT

    const int t = threadIdx.x;
    const long row0 = (long)blockIdx.x * 128;

    #pragma unroll
    for (int i = 0; i < 16; i++) {
        int lin = t + i * 128;
        int r = lin >> 4, q = lin & 15;
        long gr = row0 + r;
        float4 v = (gr < NN) ? reinterpret_cast<const float4*>(X)[gr * 16 + q]
                             : make_float4(0.f, 0.f, 0.f, 0.f);
        float* p = &Xs[r * 65 + q * 4];
        p[0] = v.x; p[1] = v.y; p[2] = v.z; p[3] = v.w;
    }
    #pragma unroll
    for (int i = t; i < 16 * NOUT; i += 128) {
        int k = (i * 4) / NOUT;
        float a = bn ? bn[k] : 1.0f;
        float4 w = reinterpret_cast<const float4*>(Wg)[i];
        reinterpret_cast<float4*>(Ws)[i] = make_float4(w.x * a, w.y * a, w.z * a, w.w * a);
    }
    if (t < NOUT) {
        float s = bias ? bias[t] : 0.0f;
        if (bn) {
            #pragma unroll 8
            for (int k = 0; k < 64; k++) s += bn[64 + k] * Wg[k * NOUT + t];
        }
        Init[t] = s;
    }
    __syncthreads();

    unsigned long long acc[NOUT / 2];
    #pragma unroll
    for (int j = 0; j < NOUT / 2; j++) {
        float2 iv = reinterpret_cast<const float2*>(Init)[j];
        asm("mov.b64 %0, {%1, %2};" : "=l"(acc[j]) : "f"(iv.x), "f"(iv.y));
    }
    const float* xr = &Xs[t * 65];
    #pragma unroll 4
    for (int k = 0; k < 64; k++) {
        float xv = xr[k];
        unsigned long long xx;
        asm("mov.b64 %0, {%1, %1};" : "=l"(xx) : "f"(xv));
        const unsigned long long* wr =
            reinterpret_cast<const unsigned long long*>(&Ws[k * NOUT]);
        #pragma unroll
        for (int j = 0; j < NOUT / 2; j++)
            asm("fma.rn.f32x2 %0, %1, %2, %0;" : "+l"(acc[j]) : "l"(xx), "l"(wr[j]));
    }

    long r = row0 + t;
    float rs = 1.0f;
    if (rowscale && r < NN) rs = rowscale[r];

    __syncthreads();   // done reading Xs -> reuse as output staging
    #pragma unroll
    for (int j = 0; j < NOUT / 2; j++) {
        float lo, hi;
        asm("mov.b64 {%0, %1}, %2;" : "=f"(lo), "=f"(hi) : "l"(acc[j]));
        Xs[t * 65 + 2 * j]     = lo * rs;
        Xs[t * 65 + 2 * j + 1] = hi * rs;
    }
    __syncthreads();
    constexpr int Q = NOUT / 4;
    #pragma unroll
    for (int i = 0; i < Q; i++) {
        int lin = t + i * 128;
        int r2 = lin / Q, q = lin % Q;
        long gr = row0 + r2;
        if (gr < NN) {
            float* p = &Xs[r2 * 65 + q * 4];
            reinterpret_cast<float4*>(out)[gr * Q + q] = make_float4(p[0], p[1], p[2], p[3]);
        }
    }
}

// ---- edge scatter: acc[dst] += hs[src]  (16 threads/edge, float4 REDG) ----
__global__ void k_scat(const float4* __restrict__ hs, float4* __restrict__ acc, int E)
{
    long idx = (long)blockIdx.x * 256 + threadIdx.x;
    if (idx >= (long)E * 16) return;
    int e = (int)(idx >> 4);
    int q = (int)(idx & 15);
    int s = g_src[e], d = g_dst[e];
    float4 v = hs[(long)s * 16 + q];
    float4* p = acc + (long)d * 16 + q;
    asm volatile("red.global.add.v4.f32 [%0], {%1,%2,%3,%4};"
                 :: "l"(p), "f"(v.x), "f"(v.y), "f"(v.z), "f"(v.w) : "memory");
}

// ---- epilogue: h = relu(dinv*(acc+hs)+b); BN stats (padded atomics) ----
template <bool ZERO_ACC>
__global__ void k_epi(const float4* hs, float4* acc, const float* __restrict__ bias,
                      float4* out, float* __restrict__ stats)
{
    __shared__ float ssum[64], ssq[64];
    int t = threadIdx.x;
    if (t < 64) { ssum[t] = 0.0f; ssq[t] = 0.0f; }
    __syncthreads();
    long idx = (long)blockIdx.x * 256 + t;
    if (idx < (long)NN * 16) {
        int v = (int)(idx >> 4);
        int q = (int)(idx & 15);
        float4 a = acc[idx];
        float4 h = hs[idx];
        float di = g_dinv[v];
        float4 b = reinterpret_cast<const float4*>(bias)[q];
        float4 o;
        o.x = fmaxf(fmaf(di, a.x + h.x, b.x), 0.0f);
        o.y = fmaxf(fmaf(di, a.y + h.y, b.y), 0.0f);
        o.z = fmaxf(fmaf(di, a.z + h.z, b.z), 0.0f);
        o.w = fmaxf(fmaf(di, a.w + h.w, b.w), 0.0f);
        out[idx] = o;
        if (ZERO_ACC) acc[idx] = make_float4(0.f, 0.f, 0.f, 0.f);
        int j = q * 4;
        atomicAdd(&ssum[j + 0], o.x); atomicAdd(&ssq[j + 0], o.x * o.x);
        atomicAdd(&ssum[j + 1], o.y); atomicAdd(&ssq[j + 1], o.y * o.y);
        atomicAdd(&ssum[j + 2], o.z); atomicAdd(&ssq[j + 2], o.z * o.z);
        atomicAdd(&ssum[j + 3], o.w); atomicAdd(&ssq[j + 3], o.w * o.w);
    }
    __syncthreads();
    if (t < 64) {
        // padded: each channel on its own 128B line -> parallel across LTS slices
        atomicAdd(&stats[t * 32], ssum[t]);
        atomicAdd(&stats[(64 + t) * 32], ssq[t]);
    }
}

// ---- BN coefficients: a = gamma*rsqrt(var+eps), c = beta - mu*a ----
__global__ void k_bn(const float* __restrict__ stats, const float* __restrict__ gamma,
                     const float* __restrict__ beta, float* __restrict__ bn)
{
    int j = threadIdx.x;
    if (j < 64) {
        float mu  = stats[j * 32] * (1.0f / NN);
        float var = stats[(64 + j) * 32] * (1.0f / NN) - mu * mu;
        float a = gamma[j] * rsqrtf(var + BN_EPS);
        bn[j] = a;
        bn[64 + j] = beta[j] - mu * a;
    }
}

extern "C" void kernel_launch(void* const* d_in, const int* in_sizes, int n_in,
                              void* d_out, int out_size)
{
    const float* x      = (const float*)d_in[0];
    const void*  ei     = d_in[1];
    const float* W1     = (const float*)d_in[2];
    const float* b1     = (const float*)d_in[3];
    const float* gamma1 = (const float*)d_in[4];
    const float* beta1  = (const float*)d_in[5];
    const float* W2     = (const float*)d_in[6];
    const float* b2     = (const float*)d_in[7];
    const float* gamma2 = (const float*)d_in[8];
    const float* beta2  = (const float*)d_in[9];
    const float* Wfc    = (const float*)d_in[10];
    const float* bfc    = (const float*)d_in[11];
    float* out = (float*)d_out;

    int E = in_sizes[1] / 2;
    if (E > EMAX) E = EMAX;

    float4 *pA, *pB, *pC;
    float *ps1, *ps2, *pbn1, *pbn2, *pdinv;
    cudaGetSymbolAddress((void**)&pA, g_bufA);
    cudaGetSymbolAddress((void**)&pB, g_bufB);
    cudaGetSymbolAddress((void**)&pC, g_bufC);
    cudaGetSymbolAddress((void**)&ps1, g_stats1);
    cudaGetSymbolAddress((void**)&ps2, g_stats2);
    cudaGetSymbolAddress((void**)&pbn1, g_bn1);
    cudaGetSymbolAddress((void**)&pbn2, g_bn2);
    cudaGetSymbolAddress((void**)&pdinv, g_dinv);

    const int smem64 = (128 * 65 + 64 * 64 + 64) * (int)sizeof(float);
    const int smem32 = (128 * 65 + 64 * 32 + 32) * (int)sizeof(float);
    cudaFuncSetAttribute(k_gemm<64>, cudaFuncAttributeMaxDynamicSharedMemorySize, smem64);
    cudaFuncSetAttribute(k_gemm<32>, cudaFuncAttributeMaxDynamicSharedMemorySize, smem32);

    const int GB = (NN + 127) / 128;
    long scat_items = (long)E * 16;
    int scat_blocks = (int)((scat_items + 255) / 256);

    k_detect<<<1, 256>>>((const unsigned int*)ei);
    k_cvt<<<(E + 255) / 256, 256>>>(ei, E);
    k_zero<<<6250, 256>>>();
    k_deg<<<(E + 255) / 256, 256>>>(E);
    k_dinv<<<(NN + 255) / 256, 256>>>();

    // layer 1
    k_gemm<64><<<GB, 128, smem64>>>(x, W1, nullptr, pdinv, nullptr, (float*)pA);
    k_scat<<<scat_blocks, 256>>>(pA, pB, E);
    k_epi<true><<<6250, 256>>>(pA, pB, b1, pA, ps1);
    k_bn<<<1, 64>>>(ps1, gamma1, beta1, pbn1);

    // layer 2
    k_gemm<64><<<GB, 128, smem64>>>((float*)pA, W2, pbn1, pdinv, nullptr, (float*)pC);
    k_scat<<<scat_blocks, 256>>>(pC, pB, E);
    k_epi<false><<<6250, 256>>>(pC, pB, b2, pC, ps2);
    k_bn<<<1, 64>>>(ps2, gamma2, beta2, pbn2);

    // final
    k_gemm<32><<<GB, 128, smem32>>>((float*)pC, Wfc, pbn2, nullptr, bfc, out);
}